// round 6
// baseline (speedup 1.0000x reference)
#include <cuda_runtime.h>
#include <cuda_bf16.h>
#include <math.h>
#include <stdint.h>

// Problem constants (B=2, S=2048, D=1024; fixed-shape problem)
#define D_DIM   1024
#define NQK     4096
#define NV      4096
#define NKNOW   8192
#define NTOT    (NQK + NV + NKNOW)   // 16384
#define MROWS   4096                 // B*S
#define KSPLIT  3072                 // 3 x 1024 bf16-split K

#define BAND_RAW 3.1e-5f
#define THR_MIN  2e-4f
#define MAX_BAND 64
#define FIX_CAP  65536

// ---------------- scratch ----------------
__device__ float g_scores[(size_t)MROWS * NTOT];            // 268 MB
__device__ __nv_bfloat16 g_Abf[(size_t)MROWS * KSPLIT];     // 25 MB  [hi | lo | hi]
__device__ __nv_bfloat16 g_Bbf[(size_t)NTOT * KSPLIT];      // 100 MB [hi | hi | lo]
__device__ float g_tau[MROWS * 4];
__device__ float g_colsum[NTOT + NKNOW];
__device__ int   g_fix_cnt;
__device__ int   g_fix_items[FIX_CAP];

// ======================= PTX helpers (plain sm_103-safe) =======================
__device__ __forceinline__ uint32_t smem_u32(const void* p) {
    uint32_t a;
    asm("{ .reg .u64 t; cvta.to.shared.u64 t, %1; cvt.u32.u64 %0, t; }" : "=r"(a) : "l"(p));
    return a;
}
#define CP_ASYNC16(dst, src) \
    asm volatile("cp.async.cg.shared.global [%0], [%1], 16;" :: "r"(dst), "l"(src))
#define CP_COMMIT() asm volatile("cp.async.commit_group;")

__device__ __forceinline__ void ldmatrix_x4(uint32_t& r0, uint32_t& r1, uint32_t& r2, uint32_t& r3, uint32_t addr) {
    asm volatile("ldmatrix.sync.aligned.m8n8.x4.shared.b16 {%0,%1,%2,%3}, [%4];"
                 : "=r"(r0), "=r"(r1), "=r"(r2), "=r"(r3) : "r"(addr));
}
__device__ __forceinline__ void mma_bf16(float* c, const uint32_t* a, const uint32_t* b) {
    asm volatile("mma.sync.aligned.m16n8k16.row.col.f32.bf16.bf16.f32 "
                 "{%0,%1,%2,%3}, {%4,%5,%6,%7}, {%8,%9}, {%0,%1,%2,%3};"
                 : "+f"(c[0]), "+f"(c[1]), "+f"(c[2]), "+f"(c[3])
                 : "r"(a[0]), "r"(a[1]), "r"(a[2]), "r"(a[3]), "r"(b[0]), "r"(b[1]));
}

// ---------------- init ----------------
__global__ void init_kernel(float* __restrict__ out, size_t aux_attn_off, size_t aux_know_off) {
    int i = blockIdx.x * blockDim.x + threadIdx.x;
    if (i < NTOT + NKNOW) g_colsum[i] = 0.f;
    if (i == 0) { out[aux_attn_off] = 0.f; out[aux_know_off] = 0.f; g_fix_cnt = 0; }
}

// ---------------- bf16-split conversion ----------------
__global__ __launch_bounds__(256) void convertA_kernel(const float* __restrict__ x) {
    int i = blockIdx.x * 256 + threadIdx.x;
    float4 v = ((const float4*)x)[i];
    int m = i >> 8;
    int k4 = (i & 255) << 2;
    __nv_bfloat16 h0 = __float2bfloat16(v.x), h1 = __float2bfloat16(v.y);
    __nv_bfloat16 h2 = __float2bfloat16(v.z), h3 = __float2bfloat16(v.w);
    __nv_bfloat16 l0 = __float2bfloat16(v.x - __bfloat162float(h0));
    __nv_bfloat16 l1 = __float2bfloat16(v.y - __bfloat162float(h1));
    __nv_bfloat16 l2 = __float2bfloat16(v.z - __bfloat162float(h2));
    __nv_bfloat16 l3 = __float2bfloat16(v.w - __bfloat162float(h3));
    __nv_bfloat16* base = g_Abf + (size_t)m * KSPLIT + k4;
    ((__nv_bfloat162*)(base))[0]        = __halves2bfloat162(h0, h1);
    ((__nv_bfloat162*)(base))[1]        = __halves2bfloat162(h2, h3);
    ((__nv_bfloat162*)(base + 1024))[0] = __halves2bfloat162(l0, l1);
    ((__nv_bfloat162*)(base + 1024))[1] = __halves2bfloat162(l2, l3);
    ((__nv_bfloat162*)(base + 2048))[0] = __halves2bfloat162(h0, h1);
    ((__nv_bfloat162*)(base + 2048))[1] = __halves2bfloat162(h2, h3);
}

__global__ __launch_bounds__(256) void convertB_kernel(
    const float* __restrict__ qk, const float* __restrict__ vem, const float* __restrict__ knm) {
    int i = blockIdx.x * 256 + threadIdx.x;
    int n = i >> 8;
    int k4 = (i & 255) << 2;
    const float* src;
    if (n < NQK)            src = qk  + (size_t)n * D_DIM;
    else if (n < NQK + NV)  src = vem + (size_t)(n - NQK) * D_DIM;
    else                    src = knm + (size_t)(n - NQK - NV) * D_DIM;
    float4 v = *(const float4*)(src + k4);
    __nv_bfloat16 h0 = __float2bfloat16(v.x), h1 = __float2bfloat16(v.y);
    __nv_bfloat16 h2 = __float2bfloat16(v.z), h3 = __float2bfloat16(v.w);
    __nv_bfloat16 l0 = __float2bfloat16(v.x - __bfloat162float(h0));
    __nv_bfloat16 l1 = __float2bfloat16(v.y - __bfloat162float(h1));
    __nv_bfloat16 l2 = __float2bfloat16(v.z - __bfloat162float(h2));
    __nv_bfloat16 l3 = __float2bfloat16(v.w - __bfloat162float(h3));
    __nv_bfloat16* base = g_Bbf + (size_t)n * KSPLIT + k4;
    ((__nv_bfloat162*)(base))[0]        = __halves2bfloat162(h0, h1);
    ((__nv_bfloat162*)(base))[1]        = __halves2bfloat162(h2, h3);
    ((__nv_bfloat162*)(base + 1024))[0] = __halves2bfloat162(h0, h1);
    ((__nv_bfloat162*)(base + 1024))[1] = __halves2bfloat162(h2, h3);
    ((__nv_bfloat162*)(base + 2048))[0] = __halves2bfloat162(l0, l1);
    ((__nv_bfloat162*)(base + 2048))[1] = __halves2bfloat162(l2, l3);
}

// ---------------- tau kernel ----------------
__global__ __launch_bounds__(128) void tau_kernel(
    const float* __restrict__ x,
    const float* __restrict__ w_attn, const float* __restrict__ b_attn,
    const float* __restrict__ w_know, const float* __restrict__ b_know)
{
    int r = blockIdx.x;
    const float* xr = x + (size_t)r * D_DIM;
    float s0 = 0.f, s1 = 0.f, s2 = 0.f, s3 = 0.f;
    for (int d = threadIdx.x; d < D_DIM; d += 128) {
        float xv = xr[d];
        s0 += xv * w_attn[d * 3 + 0];
        s1 += xv * w_attn[d * 3 + 1];
        s2 += xv * w_attn[d * 3 + 2];
        s3 += xv * w_know[d];
    }
    __shared__ float red[4][128];
    red[0][threadIdx.x] = s0; red[1][threadIdx.x] = s1;
    red[2][threadIdx.x] = s2; red[3][threadIdx.x] = s3;
    __syncthreads();
    for (int off = 64; off > 0; off >>= 1) {
        if (threadIdx.x < off) {
            red[0][threadIdx.x] += red[0][threadIdx.x + off];
            red[1][threadIdx.x] += red[1][threadIdx.x + off];
            red[2][threadIdx.x] += red[2][threadIdx.x + off];
            red[3][threadIdx.x] += red[3][threadIdx.x + off];
        }
        __syncthreads();
    }
    if (threadIdx.x == 0) {
        g_tau[r * 4 + 0] = red[0][0] + b_attn[0];
        g_tau[r * 4 + 1] = red[1][0] + b_attn[1];
        g_tau[r * 4 + 2] = red[2][0] + b_attn[2];
        g_tau[r * 4 + 3] = red[3][0] + b_know[0];
    }
}

// ---------------- mma.sync bf16 GEMM: 128x256 CTA tile, 64x64 warp tile, 4 stages ----------------
#define GSTG_A  10240                 // 128 rows * 80B
#define GSTG_B  20480                 // 256 rows * 80B
#define GSTG    (GSTG_A + GSTG_B)     // 30720
#define GNSTG   4
#define GEMM_SMEM (GNSTG * GSTG)      // 122880
#define KITERS  (KSPLIT / 32)         // 96

__device__ __forceinline__ void gload(uint32_t sbase,
    const __nv_bfloat16* gA, const __nv_bfloat16* gB, int kit, int s, int tid)
{
    const int k0 = kit * 32;
    const uint32_t st = sbase + s * GSTG;
#pragma unroll
    for (int i = 0; i < 2; i++) {                // A: 128 rows x 4 x 16B
        int c = tid + i * 256;
        int row = c >> 2, c4 = c & 3;
        CP_ASYNC16(st + row * 80 + c4 * 16, gA + (size_t)row * KSPLIT + k0 + c4 * 8);
    }
#pragma unroll
    for (int i = 0; i < 4; i++) {                // B: 256 rows x 4 x 16B
        int c = tid + i * 256;
        int row = c >> 2, c4 = c & 3;
        CP_ASYNC16(st + GSTG_A + row * 80 + c4 * 16, gB + (size_t)row * KSPLIT + k0 + c4 * 8);
    }
}

__global__ __launch_bounds__(256, 1) void gemm_bf16_kernel() {
    extern __shared__ __align__(128) char smem[];
    const uint32_t sbase = smem_u32(smem);
    const int tid = threadIdx.x;
    const int wid = tid >> 5;
    const int lid = tid & 31;
    const int m0 = blockIdx.x * 128;
    const int n0 = blockIdx.y * 256;
    const int wm = wid & 1;        // m half (64 rows)
    const int wn = wid >> 1;       // n quarter of 256 (64 cols)

    const __nv_bfloat16* gA = g_Abf + (size_t)m0 * KSPLIT;
    const __nv_bfloat16* gB = g_Bbf + (size_t)n0 * KSPLIT;

    // ldmatrix per-lane addressing
    const int arow = (lid & 7) + ((lid >> 3) & 1) * 8;
    const int acol = (lid >> 4) * 8;
    const int bq = lid >> 3;
    const int brow = (bq >> 1) * 8 + (lid & 7);
    const int bcol = (bq & 1) * 8;

    float acc[4][8][4];
#pragma unroll
    for (int i = 0; i < 4; i++)
#pragma unroll
        for (int j = 0; j < 8; j++)
#pragma unroll
            for (int q = 0; q < 4; q++) acc[i][j][q] = 0.f;

    gload(sbase, gA, gB, 0, 0, tid); CP_COMMIT();
    gload(sbase, gA, gB, 1, 1, tid); CP_COMMIT();
    gload(sbase, gA, gB, 2, 2, tid); CP_COMMIT();

#pragma unroll 1
    for (int k = 0; k < KITERS; k++) {
        if (k <= KITERS - 3)      asm volatile("cp.async.wait_group 2;");
        else if (k == KITERS - 2) asm volatile("cp.async.wait_group 1;");
        else                      asm volatile("cp.async.wait_group 0;");
        __syncthreads();

        const uint32_t sA = sbase + (k & 3) * GSTG;
        const uint32_t sB = sA + GSTG_A;
#pragma unroll
        for (int ks = 0; ks < 2; ks++) {
            const int kb = ks * 16;
            uint32_t a[4][4], b[8][2];
            const uint32_t a_base = sA + (uint32_t)(wm * 64 + arow) * 80u + (uint32_t)(kb + acol) * 2u;
#pragma unroll
            for (int i = 0; i < 4; i++)
                ldmatrix_x4(a[i][0], a[i][1], a[i][2], a[i][3], a_base + (uint32_t)(i * 16 * 80));
            const uint32_t b_base = sB + (uint32_t)(wn * 64 + brow) * 80u + (uint32_t)(kb + bcol) * 2u;
#pragma unroll
            for (int j2 = 0; j2 < 4; j2++) {
                uint32_t t0, t1, t2, t3;
                ldmatrix_x4(t0, t1, t2, t3, b_base + (uint32_t)(j2 * 16 * 80));
                b[j2 * 2][0] = t0; b[j2 * 2][1] = t1;
                b[j2 * 2 + 1][0] = t2; b[j2 * 2 + 1][1] = t3;
            }
#pragma unroll
            for (int i = 0; i < 4; i++)
#pragma unroll
                for (int j = 0; j < 8; j++)
                    mma_bf16(acc[i][j], a[i], b[j]);
        }
        if (k + 3 < KITERS) {
            gload(sbase, gA, gB, k + 3, (k + 3) & 3, tid);
            CP_COMMIT();
        }
    }

    // Epilogue: direct float2 stores (full 32B sector per quad)
    const int r4 = lid >> 2;
    const int c2 = (lid & 3) * 2;
#pragma unroll
    for (int i = 0; i < 4; i++) {
#pragma unroll
        for (int j = 0; j < 8; j++) {
            int row = m0 + wm * 64 + i * 16 + r4;
            int col = n0 + wn * 64 + j * 8 + c2;
            float* p0 = g_scores + (size_t)row * NTOT + col;
            float* p1 = g_scores + (size_t)(row + 8) * NTOT + col;
            *(float2*)p0 = make_float2(acc[i][j][0], acc[i][j][1]);
            *(float2*)p1 = make_float2(acc[i][j][2], acc[i][j][3]);
        }
    }
}

// ---------------- register-resident gate kernel ----------------
// VECOUT=false for the know gate: its output segment starts at an odd float
// offset (right after the aux_attn scalar), so vector stores would fault.
template<int N, int KSEL, bool VECOUT>
__global__ __launch_bounds__(256) void gate_t(
    int seg_off, int tau_idx, int gate_id, float* __restrict__ out, int colsum_off)
{
    constexpr int PER = N / 256;
    constexpr int P4 = PER / 4;
    const int r = blockIdx.x;
    const int tid = threadIdx.x;
    const int wid = tid >> 5, lid = tid & 31;
    const float tauv = g_tau[r * 4 + tau_idx];
    const float4* s4 = (const float4*)(g_scores + (size_t)r * NTOT + seg_off);

    __shared__ float s8[8];
    __shared__ int   i8[8];
    __shared__ unsigned whist[8][256];
    __shared__ unsigned hist[256];
    __shared__ unsigned sh_sel;
    __shared__ int sh_kneed;

    float e[PER];
    float lmax = 0.f;
    int lpos = 0;
#pragma unroll
    for (int c = 0; c < P4; c++) {
        float4 v = s4[c * 256 + tid];
        float r0 = v.x - tauv, r1 = v.y - tauv, r2 = v.z - tauv, r3 = v.w - tauv;
        float e0 = (r0 > 0.f) ? (expf(r0) - 1.f) : 0.f;
        float e1 = (r1 > 0.f) ? (expf(r1) - 1.f) : 0.f;
        float e2 = (r2 > 0.f) ? (expf(r2) - 1.f) : 0.f;
        float e3 = (r3 > 0.f) ? (expf(r3) - 1.f) : 0.f;
        e[c * 4 + 0] = e0; e[c * 4 + 1] = e1; e[c * 4 + 2] = e2; e[c * 4 + 3] = e3;
        lmax = fmaxf(fmaxf(lmax, fmaxf(e0, e1)), fmaxf(e2, e3));
        lpos += (e0 > 0.f) + (e1 > 0.f) + (e2 > 0.f) + (e3 > 0.f);
    }
#pragma unroll
    for (int o = 16; o > 0; o >>= 1) {
        lmax = fmaxf(lmax, __shfl_xor_sync(0xFFFFFFFFu, lmax, o));
        lpos += __shfl_xor_sync(0xFFFFFFFFu, lpos, o);
    }
    if (lid == 0) { s8[wid] = lmax; i8[wid] = lpos; }
    __syncthreads();
    const float gmax = fmaxf(fmaxf(fmaxf(s8[0], s8[1]), fmaxf(s8[2], s8[3])),
                             fmaxf(fmaxf(s8[4], s8[5]), fmaxf(s8[6], s8[7])));
    const int npos = i8[0] + i8[1] + i8[2] + i8[3] + i8[4] + i8[5] + i8[6] + i8[7];

    float thr = 0.f;
    if (npos > KSEL) {
        // radix pass 1: per-warp histograms on top byte, positives only
#pragma unroll
        for (int it = 0; it < 8; it++) ((unsigned*)whist)[tid + it * 256] = 0u;
        __syncthreads();
#pragma unroll
        for (int j = 0; j < PER; j++)
            if (e[j] > 0.f) atomicAdd(&whist[wid][__float_as_uint(e[j]) >> 24], 1u);
        __syncthreads();
        unsigned tot = 0;
#pragma unroll
        for (int w = 0; w < 8; w++) tot += whist[w][tid];
        hist[tid] = tot;
        __syncthreads();
        if (tid == 0) {
            unsigned cum = 0u; int sel = 0; int newk = KSEL;
            for (int bin = 255; bin >= 0; bin--) {
                unsigned h = hist[bin];
                if (cum + h >= (unsigned)KSEL) { sel = bin; newk = KSEL - (int)cum; break; }
                cum += h;
            }
            sh_sel = (unsigned)sel; sh_kneed = newk;
        }
        __syncthreads();
        unsigned prefix = sh_sel << 24;
        unsigned mask = 0xFF000000u;
        int kneed = sh_kneed;
        for (int shift = 16; shift >= 0; shift -= 8) {
            hist[tid] = 0u;
            __syncthreads();
#pragma unroll
            for (int j = 0; j < PER; j++) {
                unsigned b = __float_as_uint(e[j]);
                if (e[j] > 0.f && (b & mask) == prefix)
                    atomicAdd(&hist[(b >> shift) & 0xFFu], 1u);
            }
            __syncthreads();
            if (tid == 0) {
                unsigned cum = 0u; int sel = 0; int newk = kneed;
                for (int bin = 255; bin >= 0; bin--) {
                    unsigned h = hist[bin];
                    if (cum + h >= (unsigned)kneed) { sel = bin; newk = kneed - (int)cum; break; }
                    cum += h;
                }
                sh_sel = (unsigned)sel; sh_kneed = newk;
            }
            __syncthreads();
            prefix |= sh_sel << shift;
            mask   |= 0xFFu << shift;
            kneed   = sh_kneed;
            __syncthreads();
        }
        thr = __uint_as_float(prefix);
    }

    // band detection (uniform branch: thr identical across block)
    if (thr > THR_MIN) {
        float width = (thr + 1.0f) * BAND_RAW;
        float e_hi = thr + width, e_lo = thr - width;
        int bc = 0;
#pragma unroll
        for (int j = 0; j < PER; j++)
            bc += (e[j] >= e_lo && e[j] <= e_hi);
#pragma unroll
        for (int o = 16; o > 0; o >>= 1) bc += __shfl_xor_sync(0xFFFFFFFFu, bc, o);
        if (lid == 0) i8[wid] = bc;
        __syncthreads();
        int bandcnt = i8[0] + i8[1] + i8[2] + i8[3] + i8[4] + i8[5] + i8[6] + i8[7];
        if (bandcnt > 1) {
            if (tid == 0) {
                int idx = atomicAdd(&g_fix_cnt, 1);
                if (idx < FIX_CAP) g_fix_items[idx] = r | (gate_id << 16);
            }
            return;  // fixup kernel rewrites this row
        }
    }

    float lsum = 0.f;
#pragma unroll
    for (int j = 0; j < PER; j++)
        if (e[j] >= thr) lsum += e[j];
#pragma unroll
    for (int o = 16; o > 0; o >>= 1) lsum += __shfl_xor_sync(0xFFFFFFFFu, lsum, o);
    if (lid == 0) s8[wid] = lsum;
    __syncthreads();
    const float gsum = s8[0] + s8[1] + s8[2] + s8[3] + s8[4] + s8[5] + s8[6] + s8[7];
    const float scale = tanhf(gmax) / (gsum + 1e-8f);

    float* orow = out + (size_t)r * N;
#pragma unroll
    for (int c = 0; c < P4; c++) {
        int idx4 = c * 256 + tid;
        float v0 = e[c*4+0], v1 = e[c*4+1], v2 = e[c*4+2], v3 = e[c*4+3];
        float o0 = (v0 >= thr) ? v0 * scale : 0.f;
        float o1 = (v1 >= thr) ? v1 * scale : 0.f;
        float o2 = (v2 >= thr) ? v2 * scale : 0.f;
        float o3 = (v3 >= thr) ? v3 * scale : 0.f;
        if (VECOUT) {
            ((float4*)orow)[idx4] = make_float4(o0, o1, o2, o3);
        } else {
            orow[idx4 * 4 + 0] = o0;
            orow[idx4 * 4 + 1] = o1;
            orow[idx4 * 4 + 2] = o2;
            orow[idx4 * 4 + 3] = o3;
        }
        int base = colsum_off + idx4 * 4;
        if (v0 >= thr && v0 > 0.f) atomicAdd(&g_colsum[base + 0], o0);
        if (v1 >= thr && v1 > 0.f) atomicAdd(&g_colsum[base + 1], o1);
        if (v2 >= thr && v2 > 0.f) atomicAdd(&g_colsum[base + 2], o2);
        if (v3 >= thr && v3 > 0.f) atomicAdd(&g_colsum[base + 3], o3);
    }
}

// ---------------- radix select for fixup (smem version) ----------------
__device__ float radix_select_kth(const float* eg, int N, int ksel,
                                  unsigned* hist, unsigned* sh_sel, int* sh_kneed)
{
    const int tid = threadIdx.x;
    unsigned prefix = 0u, mask = 0u;
    int kneed = ksel;
    for (int shift = 24; shift >= 0; shift -= 8) {
        hist[tid] = 0u;
        __syncthreads();
        for (int i = tid; i < N; i += 256) {
            unsigned b = __float_as_uint(eg[i]);
            if ((b & mask) == prefix) atomicAdd(&hist[(b >> shift) & 0xFFu], 1u);
        }
        __syncthreads();
        if (tid == 0) {
            unsigned cum = 0u; int sel = 0; int newk = kneed;
            for (int bin = 255; bin >= 0; bin--) {
                unsigned h = hist[bin];
                if (cum + h >= (unsigned)kneed) { sel = bin; newk = kneed - (int)cum; break; }
                cum += h;
            }
            *sh_sel = (unsigned)sel; *sh_kneed = newk;
        }
        __syncthreads();
        prefix |= (*sh_sel) << shift;
        mask   |= 0xFFu << shift;
        kneed   = *sh_kneed;
        __syncthreads();
    }
    return __uint_as_float(prefix);
}

// ---------------- fixup kernel: exact fp64 re-ranking of ambiguous rows ----------------
__global__ __launch_bounds__(256) void fixup_kernel(
    const float* __restrict__ x,
    const float* __restrict__ qk, const float* __restrict__ vem, const float* __restrict__ knm,
    float* __restrict__ outQ, float* __restrict__ outK,
    float* __restrict__ outV, float* __restrict__ outKn)
{
    __shared__ float eg[NKNOW];
    __shared__ unsigned hist[256];
    __shared__ float red[256];
    __shared__ double dred[256];
    __shared__ unsigned sh_sel;
    __shared__ int sh_kneed;
    __shared__ int bidx[MAX_BAND];
    __shared__ double ds[MAX_BAND];
    __shared__ int keptm[MAX_BAND];
    __shared__ int sh_bc, sh_nhi;
    const int tid = threadIdx.x;

    int nfix = g_fix_cnt; if (nfix > FIX_CAP) nfix = FIX_CAP;

    for (int it = blockIdx.x; it < nfix; it += gridDim.x) {
        int code = g_fix_items[it];
        int r = code & 0xFFFF;
        int gate = code >> 16;

        int seg_off, N, ksel, tau_idx, cs_off;
        const float* emb; float* orow;
        if      (gate == 0) { seg_off = 0;        N = NQK;   ksel = 64;  tau_idx = 0; emb = qk;  orow = outQ;  cs_off = 0; }
        else if (gate == 1) { seg_off = 0;        N = NQK;   ksel = 64;  tau_idx = 1; emb = qk;  orow = outK;  cs_off = NQK; }
        else if (gate == 2) { seg_off = NQK;      N = NV;    ksel = 64;  tau_idx = 2; emb = vem; orow = outV;  cs_off = 2 * NQK; }
        else                { seg_off = NQK + NV; N = NKNOW; ksel = 128; tau_idx = 3; emb = knm; orow = outKn; cs_off = 3 * NQK; }
        orow += (size_t)r * N;

        const float* s = g_scores + (size_t)r * NTOT + seg_off;
        const float tauv = g_tau[r * 4 + tau_idx];

        float lmax = 0.f;
        for (int i = tid; i < N; i += 256) {
            float raw = s[i] - tauv;
            float e = (raw > 0.f) ? (expf(raw) - 1.f) : 0.f;
            eg[i] = e;
            lmax = fmaxf(lmax, e);
        }
        red[tid] = lmax; __syncthreads();
        for (int off = 128; off > 0; off >>= 1) {
            if (tid < off) red[tid] = fmaxf(red[tid], red[tid + off]);
            __syncthreads();
        }
        const float gmax = red[0];
        __syncthreads();

        const float thr = radix_select_kth(eg, N, ksel, hist, &sh_sel, &sh_kneed);
        const float width = (thr + 1.0f) * BAND_RAW;
        const float e_hi = thr + width, e_lo = thr - width;

        if (tid == 0) { sh_bc = 0; sh_nhi = 0; }
        __syncthreads();
        for (int i = tid; i < N; i += 256) {
            float e = eg[i];
            if (e > e_hi) atomicAdd(&sh_nhi, 1);
            else if (e >= e_lo) {
                int p = atomicAdd(&sh_bc, 1);
                if (p < MAX_BAND) bidx[p] = i;
            }
        }
        __syncthreads();
        const int bc = (sh_bc < MAX_BAND) ? sh_bc : MAX_BAND;
        const int nhi = sh_nhi;

        const float* xr = x + (size_t)r * D_DIM;
        for (int b = 0; b < bc; b++) {
            const float* er = emb + (size_t)bidx[b] * D_DIM;
            double part = 0.0;
            for (int d = tid; d < D_DIM; d += 256)
                part += (double)xr[d] * (double)er[d];
            dred[tid] = part; __syncthreads();
            for (int off = 128; off > 0; off >>= 1) {
                if (tid < off) dred[tid] += dred[tid + off];
                __syncthreads();
            }
            if (tid == 0) ds[b] = dred[0];
            __syncthreads();
        }

        if (tid == 0) {
            int need = ksel - nhi;
            for (int j = 0; j < bc; j++) {
                int rank = 0;
                for (int m = 0; m < bc; m++) if (ds[m] > ds[j]) rank++;
                keptm[j] = (rank < need) ? 1 : 0;
            }
        }
        __syncthreads();

        float lsum = 0.f;
        for (int i = tid; i < N; i += 256) {
            float e = eg[i];
            if (e > e_hi) lsum += e;
        }
        if (tid == 0) {
            for (int b = 0; b < bc; b++)
                if (keptm[b]) lsum += eg[bidx[b]];
        }
        red[tid] = lsum; __syncthreads();
        for (int off = 128; off > 0; off >>= 1) {
            if (tid < off) red[tid] += red[tid + off];
            __syncthreads();
        }
        const float scale = tanhf(gmax) / (red[0] + 1e-8f);

        for (int i = tid; i < N; i += 256) {
            float e = eg[i];
            bool keep = false;
            if (e > e_hi) keep = true;
            else if (e >= e_lo) {
                for (int b = 0; b < bc; b++)
                    if (bidx[b] == i) { keep = (keptm[b] != 0); break; }
            }
            float val = keep ? e * scale : 0.f;
            orow[i] = val;
            if (keep && e > 0.f) atomicAdd(&g_colsum[cs_off + i], val);
        }
        __syncthreads();
    }
}

// ---------------- aux finish ----------------
__global__ __launch_bounds__(256) void aux_finish_kernel(
    int colsum_off, int N, float t, float* __restrict__ outscalar)
{
    int c = blockIdx.x * blockDim.x + threadIdx.x;
    float v = 0.f;
    if (c < N) {
        float m = g_colsum[colsum_off + c] * (1.0f / (float)MROWS) - t;
        v = m * m * (float)N;
    }
    __shared__ float red[256];
    red[threadIdx.x] = v; __syncthreads();
    for (int off = 128; off > 0; off >>= 1) {
        if (threadIdx.x < off) red[threadIdx.x] += red[threadIdx.x + off];
        __syncthreads();
    }
    if (threadIdx.x == 0) atomicAdd(outscalar, red[0]);
}

// ---------------- launch ----------------
extern "C" void kernel_launch(void* const* d_in, const int* in_sizes, int n_in,
                              void* d_out, int out_size) {
    const float* x      = (const float*)d_in[0];
    const float* qk     = (const float*)d_in[1];
    const float* v      = (const float*)d_in[2];
    const float* kn     = (const float*)d_in[3];
    const float* w_attn = (const float*)d_in[4];
    const float* b_attn = (const float*)d_in[5];
    const float* w_know = (const float*)d_in[6];
    const float* b_know = (const float*)d_in[7];
    float* out = (float*)d_out;

    const size_t MN  = (size_t)MROWS * NQK;
    const size_t gQ_off = 0;
    const size_t gK_off = MN;
    const size_t gV_off = 2 * MN;
    const size_t aux_attn_off = 3 * MN;
    const size_t gKn_off = aux_attn_off + 1;     // odd offset -> know gate uses scalar stores
    const size_t aux_know_off = gKn_off + (size_t)MROWS * NKNOW;

    cudaFuncSetAttribute(gemm_bf16_kernel, cudaFuncAttributeMaxDynamicSharedMemorySize, GEMM_SMEM);

    init_kernel<<<(NTOT + NKNOW + 255) / 256, 256>>>(out, aux_attn_off, aux_know_off);

    convertA_kernel<<<(MROWS * D_DIM / 4) / 256, 256>>>(x);
    convertB_kernel<<<(NTOT * D_DIM / 4) / 256, 256>>>(qk, v, kn);

    tau_kernel<<<MROWS, 128>>>(x, w_attn, b_attn, w_know, b_know);

    gemm_bf16_kernel<<<dim3(MROWS / 128, NTOT / 256), 256, GEMM_SMEM>>>();

    gate_t<NQK,   64,  true ><<<MROWS, 256>>>(0,         0, 0, out + gQ_off,  0);
    gate_t<NQK,   64,  true ><<<MROWS, 256>>>(0,         1, 1, out + gK_off,  NQK);
    gate_t<NV,    64,  true ><<<MROWS, 256>>>(NQK,       2, 2, out + gV_off,  2 * NQK);
    gate_t<NKNOW, 128, false><<<MROWS, 256>>>(NQK + NV,  3, 3, out + gKn_off, 3 * NQK);

    fixup_kernel<<<256, 256>>>(x, qk, v, kn,
                               out + gQ_off, out + gK_off, out + gV_off, out + gKn_off);

    aux_finish_kernel<<<NQK / 256,   256>>>(0,       NQK,   1.0f / NQK,   out + aux_attn_off);
    aux_finish_kernel<<<NQK / 256,   256>>>(NQK,     NQK,   1.0f / NQK,   out + aux_attn_off);
    aux_finish_kernel<<<NV / 256,    256>>>(2 * NQK, NV,    1.0f / NV,    out + aux_attn_off);
    aux_finish_kernel<<<NKNOW / 256, 256>>>(3 * NQK, NKNOW, 1.0f / NKNOW, out + aux_know_off);
}

// round 7
// speedup vs baseline: 1.0181x; 1.0181x over previous
#include <cuda_runtime.h>
#include <cuda_bf16.h>
#include <math.h>
#include <stdint.h>

// Problem constants (B=2, S=2048, D=1024; fixed-shape problem)
#define D_DIM   1024
#define NQK     4096
#define NV      4096
#define NKNOW   8192
#define NTOT    (NQK + NV + NKNOW)   // 16384
#define MROWS   4096                 // B*S
#define KSPLIT  3072                 // 3 x 1024 bf16-split K

#define BAND_RAW 3.1e-5f
#define THR_MIN  2e-4f
#define MAX_BAND 64
#define FIX_CAP  65536

// ---------------- scratch ----------------
__device__ float g_scores[(size_t)MROWS * NTOT];            // 268 MB
__device__ __nv_bfloat16 g_Abf[(size_t)MROWS * KSPLIT];     // 25 MB  [hi | lo | hi]
__device__ __nv_bfloat16 g_Bbf[(size_t)NTOT * KSPLIT];      // 100 MB [hi | hi | lo]
__device__ float g_tau[MROWS * 4];
__device__ float g_colsum[NTOT + NKNOW];
__device__ int   g_fix_cnt;
__device__ int   g_fix_items[FIX_CAP];

// ======================= PTX helpers (plain sm_103-safe) =======================
__device__ __forceinline__ uint32_t smem_u32(const void* p) {
    uint32_t a;
    asm("{ .reg .u64 t; cvta.to.shared.u64 t, %1; cvt.u32.u64 %0, t; }" : "=r"(a) : "l"(p));
    return a;
}
#define CP_ASYNC16(dst, src) \
    asm volatile("cp.async.cg.shared.global [%0], [%1], 16;" :: "r"(dst), "l"(src))
#define CP_COMMIT() asm volatile("cp.async.commit_group;")

__device__ __forceinline__ void ldmatrix_x4(uint32_t& r0, uint32_t& r1, uint32_t& r2, uint32_t& r3, uint32_t addr) {
    asm volatile("ldmatrix.sync.aligned.m8n8.x4.shared.b16 {%0,%1,%2,%3}, [%4];"
                 : "=r"(r0), "=r"(r1), "=r"(r2), "=r"(r3) : "r"(addr));
}
__device__ __forceinline__ void mma_bf16(float* c, const uint32_t* a, const uint32_t* b) {
    asm volatile("mma.sync.aligned.m16n8k16.row.col.f32.bf16.bf16.f32 "
                 "{%0,%1,%2,%3}, {%4,%5,%6,%7}, {%8,%9}, {%0,%1,%2,%3};"
                 : "+f"(c[0]), "+f"(c[1]), "+f"(c[2]), "+f"(c[3])
                 : "r"(a[0]), "r"(a[1]), "r"(a[2]), "r"(a[3]), "r"(b[0]), "r"(b[1]));
}

// ---------------- init ----------------
__global__ void init_kernel(float* __restrict__ out, size_t aux_attn_off, size_t aux_know_off) {
    int i = blockIdx.x * blockDim.x + threadIdx.x;
    if (i < NTOT + NKNOW) g_colsum[i] = 0.f;
    if (i == 0) { out[aux_attn_off] = 0.f; out[aux_know_off] = 0.f; g_fix_cnt = 0; }
}

// ---------------- bf16-split conversion ----------------
__global__ __launch_bounds__(256) void convertA_kernel(const float* __restrict__ x) {
    int i = blockIdx.x * 256 + threadIdx.x;
    float4 v = ((const float4*)x)[i];
    int m = i >> 8;
    int k4 = (i & 255) << 2;
    __nv_bfloat16 h0 = __float2bfloat16(v.x), h1 = __float2bfloat16(v.y);
    __nv_bfloat16 h2 = __float2bfloat16(v.z), h3 = __float2bfloat16(v.w);
    __nv_bfloat16 l0 = __float2bfloat16(v.x - __bfloat162float(h0));
    __nv_bfloat16 l1 = __float2bfloat16(v.y - __bfloat162float(h1));
    __nv_bfloat16 l2 = __float2bfloat16(v.z - __bfloat162float(h2));
    __nv_bfloat16 l3 = __float2bfloat16(v.w - __bfloat162float(h3));
    __nv_bfloat16* base = g_Abf + (size_t)m * KSPLIT + k4;
    ((__nv_bfloat162*)(base))[0]        = __halves2bfloat162(h0, h1);
    ((__nv_bfloat162*)(base))[1]        = __halves2bfloat162(h2, h3);
    ((__nv_bfloat162*)(base + 1024))[0] = __halves2bfloat162(l0, l1);
    ((__nv_bfloat162*)(base + 1024))[1] = __halves2bfloat162(l2, l3);
    ((__nv_bfloat162*)(base + 2048))[0] = __halves2bfloat162(h0, h1);
    ((__nv_bfloat162*)(base + 2048))[1] = __halves2bfloat162(h2, h3);
}

__global__ __launch_bounds__(256) void convertB_kernel(
    const float* __restrict__ qk, const float* __restrict__ vem, const float* __restrict__ knm) {
    int i = blockIdx.x * 256 + threadIdx.x;
    int n = i >> 8;
    int k4 = (i & 255) << 2;
    const float* src;
    if (n < NQK)            src = qk  + (size_t)n * D_DIM;
    else if (n < NQK + NV)  src = vem + (size_t)(n - NQK) * D_DIM;
    else                    src = knm + (size_t)(n - NQK - NV) * D_DIM;
    float4 v = *(const float4*)(src + k4);
    __nv_bfloat16 h0 = __float2bfloat16(v.x), h1 = __float2bfloat16(v.y);
    __nv_bfloat16 h2 = __float2bfloat16(v.z), h3 = __float2bfloat16(v.w);
    __nv_bfloat16 l0 = __float2bfloat16(v.x - __bfloat162float(h0));
    __nv_bfloat16 l1 = __float2bfloat16(v.y - __bfloat162float(h1));
    __nv_bfloat16 l2 = __float2bfloat16(v.z - __bfloat162float(h2));
    __nv_bfloat16 l3 = __float2bfloat16(v.w - __bfloat162float(h3));
    __nv_bfloat16* base = g_Bbf + (size_t)n * KSPLIT + k4;
    ((__nv_bfloat162*)(base))[0]        = __halves2bfloat162(h0, h1);
    ((__nv_bfloat162*)(base))[1]        = __halves2bfloat162(h2, h3);
    ((__nv_bfloat162*)(base + 1024))[0] = __halves2bfloat162(h0, h1);
    ((__nv_bfloat162*)(base + 1024))[1] = __halves2bfloat162(h2, h3);
    ((__nv_bfloat162*)(base + 2048))[0] = __halves2bfloat162(l0, l1);
    ((__nv_bfloat162*)(base + 2048))[1] = __halves2bfloat162(l2, l3);
}

// ---------------- tau kernel ----------------
__global__ __launch_bounds__(128) void tau_kernel(
    const float* __restrict__ x,
    const float* __restrict__ w_attn, const float* __restrict__ b_attn,
    const float* __restrict__ w_know, const float* __restrict__ b_know)
{
    int r = blockIdx.x;
    const float* xr = x + (size_t)r * D_DIM;
    float s0 = 0.f, s1 = 0.f, s2 = 0.f, s3 = 0.f;
    for (int d = threadIdx.x; d < D_DIM; d += 128) {
        float xv = xr[d];
        s0 += xv * w_attn[d * 3 + 0];
        s1 += xv * w_attn[d * 3 + 1];
        s2 += xv * w_attn[d * 3 + 2];
        s3 += xv * w_know[d];
    }
    __shared__ float red[4][128];
    red[0][threadIdx.x] = s0; red[1][threadIdx.x] = s1;
    red[2][threadIdx.x] = s2; red[3][threadIdx.x] = s3;
    __syncthreads();
    for (int off = 64; off > 0; off >>= 1) {
        if (threadIdx.x < off) {
            red[0][threadIdx.x] += red[0][threadIdx.x + off];
            red[1][threadIdx.x] += red[1][threadIdx.x + off];
            red[2][threadIdx.x] += red[2][threadIdx.x + off];
            red[3][threadIdx.x] += red[3][threadIdx.x + off];
        }
        __syncthreads();
    }
    if (threadIdx.x == 0) {
        g_tau[r * 4 + 0] = red[0][0] + b_attn[0];
        g_tau[r * 4 + 1] = red[1][0] + b_attn[1];
        g_tau[r * 4 + 2] = red[2][0] + b_attn[2];
        g_tau[r * 4 + 3] = red[3][0] + b_know[0];
    }
}

// ---------------- mma.sync bf16 GEMM: 128x128x32 tiles, 64x32 warp tiles, 4 stages, 2 CTA/SM ----------------
#define GSTG_A  10240                 // 128 rows * 80B
#define GSTG_B  10240                 // 128 rows * 80B
#define GSTG    (GSTG_A + GSTG_B)     // 20480
#define GNSTG   4
#define GEMM_SMEM (GNSTG * GSTG)      // 81920 per CTA; 2 CTAs = 160KB < 228KB
#define KITERS  (KSPLIT / 32)         // 96

__device__ __forceinline__ void gload(uint32_t sbase,
    const __nv_bfloat16* gA, const __nv_bfloat16* gB, int kit, int s, int tid)
{
    const int k0 = kit * 32;
    const uint32_t st = sbase + s * GSTG;
#pragma unroll
    for (int i = 0; i < 2; i++) {                // A: 128 rows x 4 x 16B
        int c = tid + i * 256;
        int row = c >> 2, c4 = c & 3;
        CP_ASYNC16(st + row * 80 + c4 * 16, gA + (size_t)row * KSPLIT + k0 + c4 * 8);
    }
#pragma unroll
    for (int i = 0; i < 2; i++) {                // B: 128 rows x 4 x 16B
        int c = tid + i * 256;
        int row = c >> 2, c4 = c & 3;
        CP_ASYNC16(st + GSTG_A + row * 80 + c4 * 16, gB + (size_t)row * KSPLIT + k0 + c4 * 8);
    }
}

__global__ __launch_bounds__(256, 2) void gemm_bf16_kernel(int moff) {
    extern __shared__ __align__(128) char smem[];
    const uint32_t sbase = smem_u32(smem);
    const int tid = threadIdx.x;
    const int wid = tid >> 5;
    const int lid = tid & 31;
    const int m0 = moff + blockIdx.x * 128;
    const int n0 = blockIdx.y * 128;
    const int wm = wid & 1;        // m half (64 rows)
    const int wn = wid >> 1;       // n quarter (32 cols)

    const __nv_bfloat16* gA = g_Abf + (size_t)m0 * KSPLIT;
    const __nv_bfloat16* gB = g_Bbf + (size_t)n0 * KSPLIT;

    // ldmatrix per-lane addressing
    const int arow = (lid & 7) + ((lid >> 3) & 1) * 8;
    const int acol = (lid >> 4) * 8;
    const int bq = lid >> 3;
    const int brow = (bq >> 1) * 8 + (lid & 7);
    const int bcol = (bq & 1) * 8;

    float acc[4][4][4];
#pragma unroll
    for (int i = 0; i < 4; i++)
#pragma unroll
        for (int j = 0; j < 4; j++)
#pragma unroll
            for (int q = 0; q < 4; q++) acc[i][j][q] = 0.f;

    gload(sbase, gA, gB, 0, 0, tid); CP_COMMIT();
    gload(sbase, gA, gB, 1, 1, tid); CP_COMMIT();
    gload(sbase, gA, gB, 2, 2, tid); CP_COMMIT();

#pragma unroll 1
    for (int k = 0; k < KITERS; k++) {
        if (k <= KITERS - 3)      asm volatile("cp.async.wait_group 2;");
        else if (k == KITERS - 2) asm volatile("cp.async.wait_group 1;");
        else                      asm volatile("cp.async.wait_group 0;");
        __syncthreads();

        const uint32_t sA = sbase + (k & 3) * GSTG;
        const uint32_t sB = sA + GSTG_A;
#pragma unroll
        for (int ks = 0; ks < 2; ks++) {
            const int kb = ks * 16;
            uint32_t a[4][4], b[4][2];
            const uint32_t a_base = sA + (uint32_t)(wm * 64 + arow) * 80u + (uint32_t)(kb + acol) * 2u;
#pragma unroll
            for (int i = 0; i < 4; i++)
                ldmatrix_x4(a[i][0], a[i][1], a[i][2], a[i][3], a_base + (uint32_t)(i * 16 * 80));
            const uint32_t b_base = sB + (uint32_t)(wn * 32 + brow) * 80u + (uint32_t)(kb + bcol) * 2u;
#pragma unroll
            for (int j2 = 0; j2 < 2; j2++) {
                uint32_t t0, t1, t2, t3;
                ldmatrix_x4(t0, t1, t2, t3, b_base + (uint32_t)(j2 * 16 * 80));
                b[j2 * 2][0] = t0; b[j2 * 2][1] = t1;
                b[j2 * 2 + 1][0] = t2; b[j2 * 2 + 1][1] = t3;
            }
#pragma unroll
            for (int i = 0; i < 4; i++)
#pragma unroll
                for (int j = 0; j < 4; j++)
                    mma_bf16(acc[i][j], a[i], b[j]);
        }
        if (k + 3 < KITERS) {
            gload(sbase, gA, gB, k + 3, (k + 3) & 3, tid);
            CP_COMMIT();
        }
    }

    // Epilogue: direct float2 stores (full 32B sector per quad)
    const int r4 = lid >> 2;
    const int c2 = (lid & 3) * 2;
#pragma unroll
    for (int i = 0; i < 4; i++) {
#pragma unroll
        for (int j = 0; j < 4; j++) {
            int row = m0 + wm * 64 + i * 16 + r4;
            int col = n0 + wn * 32 + j * 8 + c2;
            float* p0 = g_scores + (size_t)row * NTOT + col;
            float* p1 = g_scores + (size_t)(row + 8) * NTOT + col;
            *(float2*)p0 = make_float2(acc[i][j][0], acc[i][j][1]);
            *(float2*)p1 = make_float2(acc[i][j][2], acc[i][j][3]);
        }
    }
}

// ---------------- register-resident gate kernel ----------------
// VECOUT=false for the know gate: its output segment starts at an odd float offset.
template<int N, int KSEL, bool VECOUT>
__global__ __launch_bounds__(256) void gate_t(
    int row0, int seg_off, int tau_idx, int gate_id, float* __restrict__ out, int colsum_off)
{
    constexpr int PER = N / 256;
    constexpr int P4 = PER / 4;
    const int r = row0 + blockIdx.x;
    const int tid = threadIdx.x;
    const int wid = tid >> 5, lid = tid & 31;
    const float tauv = g_tau[r * 4 + tau_idx];
    const float4* s4 = (const float4*)(g_scores + (size_t)r * NTOT + seg_off);

    __shared__ float s8[8];
    __shared__ int   i8[8];
    __shared__ unsigned whist[8][256];
    __shared__ unsigned hist[256];
    __shared__ unsigned sh_sel;
    __shared__ int sh_kneed;

    float e[PER];
    float lmax = 0.f;
    int lpos = 0;
#pragma unroll
    for (int c = 0; c < P4; c++) {
        float4 v = s4[c * 256 + tid];
        float r0 = v.x - tauv, r1 = v.y - tauv, r2 = v.z - tauv, r3 = v.w - tauv;
        float e0 = (r0 > 0.f) ? (expf(r0) - 1.f) : 0.f;
        float e1 = (r1 > 0.f) ? (expf(r1) - 1.f) : 0.f;
        float e2 = (r2 > 0.f) ? (expf(r2) - 1.f) : 0.f;
        float e3 = (r3 > 0.f) ? (expf(r3) - 1.f) : 0.f;
        e[c * 4 + 0] = e0; e[c * 4 + 1] = e1; e[c * 4 + 2] = e2; e[c * 4 + 3] = e3;
        lmax = fmaxf(fmaxf(lmax, fmaxf(e0, e1)), fmaxf(e2, e3));
        lpos += (e0 > 0.f) + (e1 > 0.f) + (e2 > 0.f) + (e3 > 0.f);
    }
#pragma unroll
    for (int o = 16; o > 0; o >>= 1) {
        lmax = fmaxf(lmax, __shfl_xor_sync(0xFFFFFFFFu, lmax, o));
        lpos += __shfl_xor_sync(0xFFFFFFFFu, lpos, o);
    }
    if (lid == 0) { s8[wid] = lmax; i8[wid] = lpos; }
    __syncthreads();
    const float gmax = fmaxf(fmaxf(fmaxf(s8[0], s8[1]), fmaxf(s8[2], s8[3])),
                             fmaxf(fmaxf(s8[4], s8[5]), fmaxf(s8[6], s8[7])));
    const int npos = i8[0] + i8[1] + i8[2] + i8[3] + i8[4] + i8[5] + i8[6] + i8[7];

    float thr = 0.f;
    if (npos > KSEL) {
#pragma unroll
        for (int it = 0; it < 8; it++) ((unsigned*)whist)[tid + it * 256] = 0u;
        __syncthreads();
#pragma unroll
        for (int j = 0; j < PER; j++)
            if (e[j] > 0.f) atomicAdd(&whist[wid][__float_as_uint(e[j]) >> 24], 1u);
        __syncthreads();
        unsigned tot = 0;
#pragma unroll
        for (int w = 0; w < 8; w++) tot += whist[w][tid];
        hist[tid] = tot;
        __syncthreads();
        if (tid == 0) {
            unsigned cum = 0u; int sel = 0; int newk = KSEL;
            for (int bin = 255; bin >= 0; bin--) {
                unsigned h = hist[bin];
                if (cum + h >= (unsigned)KSEL) { sel = bin; newk = KSEL - (int)cum; break; }
                cum += h;
            }
            sh_sel = (unsigned)sel; sh_kneed = newk;
        }
        __syncthreads();
        unsigned prefix = sh_sel << 24;
        unsigned mask = 0xFF000000u;
        int kneed = sh_kneed;
        for (int shift = 16; shift >= 0; shift -= 8) {
            hist[tid] = 0u;
            __syncthreads();
#pragma unroll
            for (int j = 0; j < PER; j++) {
                unsigned b = __float_as_uint(e[j]);
                if (e[j] > 0.f && (b & mask) == prefix)
                    atomicAdd(&hist[(b >> shift) & 0xFFu], 1u);
            }
            __syncthreads();
            if (tid == 0) {
                unsigned cum = 0u; int sel = 0; int newk = kneed;
                for (int bin = 255; bin >= 0; bin--) {
                    unsigned h = hist[bin];
                    if (cum + h >= (unsigned)kneed) { sel = bin; newk = kneed - (int)cum; break; }
                    cum += h;
                }
                sh_sel = (unsigned)sel; sh_kneed = newk;
            }
            __syncthreads();
            prefix |= sh_sel << shift;
            mask   |= 0xFFu << shift;
            kneed   = sh_kneed;
            __syncthreads();
        }
        thr = __uint_as_float(prefix);
    }

    if (thr > THR_MIN) {
        float width = (thr + 1.0f) * BAND_RAW;
        float e_hi = thr + width, e_lo = thr - width;
        int bc = 0;
#pragma unroll
        for (int j = 0; j < PER; j++)
            bc += (e[j] >= e_lo && e[j] <= e_hi);
#pragma unroll
        for (int o = 16; o > 0; o >>= 1) bc += __shfl_xor_sync(0xFFFFFFFFu, bc, o);
        if (lid == 0) i8[wid] = bc;
        __syncthreads();
        int bandcnt = i8[0] + i8[1] + i8[2] + i8[3] + i8[4] + i8[5] + i8[6] + i8[7];
        if (bandcnt > 1) {
            if (tid == 0) {
                int idx = atomicAdd(&g_fix_cnt, 1);
                if (idx < FIX_CAP) g_fix_items[idx] = r | (gate_id << 16);
            }
            return;
        }
    }

    float lsum = 0.f;
#pragma unroll
    for (int j = 0; j < PER; j++)
        if (e[j] >= thr) lsum += e[j];
#pragma unroll
    for (int o = 16; o > 0; o >>= 1) lsum += __shfl_xor_sync(0xFFFFFFFFu, lsum, o);
    if (lid == 0) s8[wid] = lsum;
    __syncthreads();
    const float gsum = s8[0] + s8[1] + s8[2] + s8[3] + s8[4] + s8[5] + s8[6] + s8[7];
    const float scale = tanhf(gmax) / (gsum + 1e-8f);

    float* orow = out + (size_t)r * N;
#pragma unroll
    for (int c = 0; c < P4; c++) {
        int idx4 = c * 256 + tid;
        float v0 = e[c*4+0], v1 = e[c*4+1], v2 = e[c*4+2], v3 = e[c*4+3];
        float o0 = (v0 >= thr) ? v0 * scale : 0.f;
        float o1 = (v1 >= thr) ? v1 * scale : 0.f;
        float o2 = (v2 >= thr) ? v2 * scale : 0.f;
        float o3 = (v3 >= thr) ? v3 * scale : 0.f;
        if (VECOUT) {
            ((float4*)orow)[idx4] = make_float4(o0, o1, o2, o3);
        } else {
            orow[idx4 * 4 + 0] = o0;
            orow[idx4 * 4 + 1] = o1;
            orow[idx4 * 4 + 2] = o2;
            orow[idx4 * 4 + 3] = o3;
        }
        int base = colsum_off + idx4 * 4;
        if (v0 >= thr && v0 > 0.f) atomicAdd(&g_colsum[base + 0], o0);
        if (v1 >= thr && v1 > 0.f) atomicAdd(&g_colsum[base + 1], o1);
        if (v2 >= thr && v2 > 0.f) atomicAdd(&g_colsum[base + 2], o2);
        if (v3 >= thr && v3 > 0.f) atomicAdd(&g_colsum[base + 3], o3);
    }
}

// ---------------- radix select for fixup (smem version) ----------------
__device__ float radix_select_kth(const float* eg, int N, int ksel,
                                  unsigned* hist, unsigned* sh_sel, int* sh_kneed)
{
    const int tid = threadIdx.x;
    unsigned prefix = 0u, mask = 0u;
    int kneed = ksel;
    for (int shift = 24; shift >= 0; shift -= 8) {
        hist[tid] = 0u;
        __syncthreads();
        for (int i = tid; i < N; i += 256) {
            unsigned b = __float_as_uint(eg[i]);
            if ((b & mask) == prefix) atomicAdd(&hist[(b >> shift) & 0xFFu], 1u);
        }
        __syncthreads();
        if (tid == 0) {
            unsigned cum = 0u; int sel = 0; int newk = kneed;
            for (int bin = 255; bin >= 0; bin--) {
                unsigned h = hist[bin];
                if (cum + h >= (unsigned)kneed) { sel = bin; newk = kneed - (int)cum; break; }
                cum += h;
            }
            *sh_sel = (unsigned)sel; *sh_kneed = newk;
        }
        __syncthreads();
        prefix |= (*sh_sel) << shift;
        mask   |= 0xFFu << shift;
        kneed   = *sh_kneed;
        __syncthreads();
    }
    return __uint_as_float(prefix);
}

// ---------------- fixup kernel: exact fp64 re-ranking of ambiguous rows ----------------
__global__ __launch_bounds__(256) void fixup_kernel(
    const float* __restrict__ x,
    const float* __restrict__ qk, const float* __restrict__ vem, const float* __restrict__ knm,
    float* __restrict__ outQ, float* __restrict__ outK,
    float* __restrict__ outV, float* __restrict__ outKn)
{
    __shared__ float eg[NKNOW];
    __shared__ unsigned hist[256];
    __shared__ float red[256];
    __shared__ double dred[256];
    __shared__ unsigned sh_sel;
    __shared__ int sh_kneed;
    __shared__ int bidx[MAX_BAND];
    __shared__ double ds[MAX_BAND];
    __shared__ int keptm[MAX_BAND];
    __shared__ int sh_bc, sh_nhi;
    const int tid = threadIdx.x;

    int nfix = g_fix_cnt; if (nfix > FIX_CAP) nfix = FIX_CAP;

    for (int it = blockIdx.x; it < nfix; it += gridDim.x) {
        int code = g_fix_items[it];
        int r = code & 0xFFFF;
        int gate = code >> 16;

        int seg_off, N, ksel, tau_idx, cs_off;
        const float* emb; float* orow;
        if      (gate == 0) { seg_off = 0;        N = NQK;   ksel = 64;  tau_idx = 0; emb = qk;  orow = outQ;  cs_off = 0; }
        else if (gate == 1) { seg_off = 0;        N = NQK;   ksel = 64;  tau_idx = 1; emb = qk;  orow = outK;  cs_off = NQK; }
        else if (gate == 2) { seg_off = NQK;      N = NV;    ksel = 64;  tau_idx = 2; emb = vem; orow = outV;  cs_off = 2 * NQK; }
        else                { seg_off = NQK + NV; N = NKNOW; ksel = 128; tau_idx = 3; emb = knm; orow = outKn; cs_off = 3 * NQK; }
        orow += (size_t)r * N;

        const float* s = g_scores + (size_t)r * NTOT + seg_off;
        const float tauv = g_tau[r * 4 + tau_idx];

        float lmax = 0.f;
        for (int i = tid; i < N; i += 256) {
            float raw = s[i] - tauv;
            float e = (raw > 0.f) ? (expf(raw) - 1.f) : 0.f;
            eg[i] = e;
            lmax = fmaxf(lmax, e);
        }
        red[tid] = lmax; __syncthreads();
        for (int off = 128; off > 0; off >>= 1) {
            if (tid < off) red[tid] = fmaxf(red[tid], red[tid + off]);
            __syncthreads();
        }
        const float gmax = red[0];
        __syncthreads();

        const float thr = radix_select_kth(eg, N, ksel, hist, &sh_sel, &sh_kneed);
        const float width = (thr + 1.0f) * BAND_RAW;
        const float e_hi = thr + width, e_lo = thr - width;

        if (tid == 0) { sh_bc = 0; sh_nhi = 0; }
        __syncthreads();
        for (int i = tid; i < N; i += 256) {
            float e = eg[i];
            if (e > e_hi) atomicAdd(&sh_nhi, 1);
            else if (e >= e_lo) {
                int p = atomicAdd(&sh_bc, 1);
                if (p < MAX_BAND) bidx[p] = i;
            }
        }
        __syncthreads();
        const int bc = (sh_bc < MAX_BAND) ? sh_bc : MAX_BAND;
        const int nhi = sh_nhi;

        const float* xr = x + (size_t)r * D_DIM;
        for (int b = 0; b < bc; b++) {
            const float* er = emb + (size_t)bidx[b] * D_DIM;
            double part = 0.0;
            for (int d = tid; d < D_DIM; d += 256)
                part += (double)xr[d] * (double)er[d];
            dred[tid] = part; __syncthreads();
            for (int off = 128; off > 0; off >>= 1) {
                if (tid < off) dred[tid] += dred[tid + off];
                __syncthreads();
            }
            if (tid == 0) ds[b] = dred[0];
            __syncthreads();
        }

        if (tid == 0) {
            int need = ksel - nhi;
            for (int j = 0; j < bc; j++) {
                int rank = 0;
                for (int m = 0; m < bc; m++) if (ds[m] > ds[j]) rank++;
                keptm[j] = (rank < need) ? 1 : 0;
            }
        }
        __syncthreads();

        float lsum = 0.f;
        for (int i = tid; i < N; i += 256) {
            float e = eg[i];
            if (e > e_hi) lsum += e;
        }
        if (tid == 0) {
            for (int b = 0; b < bc; b++)
                if (keptm[b]) lsum += eg[bidx[b]];
        }
        red[tid] = lsum; __syncthreads();
        for (int off = 128; off > 0; off >>= 1) {
            if (tid < off) red[tid] += red[tid + off];
            __syncthreads();
        }
        const float scale = tanhf(gmax) / (red[0] + 1e-8f);

        for (int i = tid; i < N; i += 256) {
            float e = eg[i];
            bool keep = false;
            if (e > e_hi) keep = true;
            else if (e >= e_lo) {
                for (int b = 0; b < bc; b++)
                    if (bidx[b] == i) { keep = (keptm[b] != 0); break; }
            }
            float val = keep ? e * scale : 0.f;
            orow[i] = val;
            if (keep && e > 0.f) atomicAdd(&g_colsum[cs_off + i], val);
        }
        __syncthreads();
    }
}

// ---------------- aux finish ----------------
__global__ __launch_bounds__(256) void aux_finish_kernel(
    int colsum_off, int N, float t, float* __restrict__ outscalar)
{
    int c = blockIdx.x * blockDim.x + threadIdx.x;
    float v = 0.f;
    if (c < N) {
        float m = g_colsum[colsum_off + c] * (1.0f / (float)MROWS) - t;
        v = m * m * (float)N;
    }
    __shared__ float red[256];
    red[threadIdx.x] = v; __syncthreads();
    for (int off = 128; off > 0; off >>= 1) {
        if (threadIdx.x < off) red[threadIdx.x] += red[threadIdx.x + off];
        __syncthreads();
    }
    if (threadIdx.x == 0) atomicAdd(outscalar, red[0]);
}

// ---------------- launch ----------------
extern "C" void kernel_launch(void* const* d_in, const int* in_sizes, int n_in,
                              void* d_out, int out_size) {
    const float* x      = (const float*)d_in[0];
    const float* qk     = (const float*)d_in[1];
    const float* v      = (const float*)d_in[2];
    const float* kn     = (const float*)d_in[3];
    const float* w_attn = (const float*)d_in[4];
    const float* b_attn = (const float*)d_in[5];
    const float* w_know = (const float*)d_in[6];
    const float* b_know = (const float*)d_in[7];
    float* out = (float*)d_out;

    const size_t MN  = (size_t)MROWS * NQK;
    const size_t gQ_off = 0;
    const size_t gK_off = MN;
    const size_t gV_off = 2 * MN;
    const size_t aux_attn_off = 3 * MN;
    const size_t gKn_off = aux_attn_off + 1;     // odd offset -> know gate uses scalar stores
    const size_t aux_know_off = gKn_off + (size_t)MROWS * NKNOW;

    float* outQ  = out + gQ_off;
    float* outK  = out + gK_off;
    float* outV  = out + gV_off;
    float* outKn = out + gKn_off;

    // One side stream + events for fork-join overlap (created once; capture-legal).
    static cudaStream_t s_side = nullptr;
    static cudaEvent_t evG1 = nullptr, evS = nullptr;
    if (s_side == nullptr) {
        cudaStreamCreateWithFlags(&s_side, cudaStreamNonBlocking);
        cudaEventCreateWithFlags(&evG1, cudaEventDisableTiming);
        cudaEventCreateWithFlags(&evS, cudaEventDisableTiming);
    }

    cudaFuncSetAttribute(gemm_bf16_kernel, cudaFuncAttributeMaxDynamicSharedMemorySize, GEMM_SMEM);

    init_kernel<<<(NTOT + NKNOW + 255) / 256, 256>>>(out, aux_attn_off, aux_know_off);
    convertA_kernel<<<(MROWS * D_DIM / 4) / 256, 256>>>(x);
    convertB_kernel<<<(NTOT * D_DIM / 4) / 256, 256>>>(qk, v, kn);
    tau_kernel<<<MROWS, 128>>>(x, w_attn, b_attn, w_know, b_know);

    // GEMM half 1 (rows 0..2047)
    gemm_bf16_kernel<<<dim3(MROWS / 256, NTOT / 128), 256, GEMM_SMEM>>>(0);
    cudaEventRecord(evG1, 0);

    // GEMM half 2 (rows 2048..4095) on main stream
    gemm_bf16_kernel<<<dim3(MROWS / 256, NTOT / 128), 256, GEMM_SMEM>>>(MROWS / 2);

    // Gates for rows 0..2047 overlap with GEMM half 2 on the side stream
    cudaStreamWaitEvent(s_side, evG1, 0);
    const int H = MROWS / 2;
    gate_t<NQK,   64,  true ><<<H, 256, 0, s_side>>>(0, 0,        0, 0, outQ,  0);
    gate_t<NQK,   64,  true ><<<H, 256, 0, s_side>>>(0, 0,        1, 1, outK,  NQK);
    gate_t<NV,    64,  true ><<<H, 256, 0, s_side>>>(0, NQK,      2, 2, outV,  2 * NQK);
    gate_t<NKNOW, 128, false><<<H, 256, 0, s_side>>>(0, NQK + NV, 3, 3, outKn, 3 * NQK);
    cudaEventRecord(evS, s_side);

    // Gates for rows 2048..4095 on main stream (after GEMM half 2)
    gate_t<NQK,   64,  true ><<<H, 256>>>(H, 0,        0, 0, outQ,  0);
    gate_t<NQK,   64,  true ><<<H, 256>>>(H, 0,        1, 1, outK,  NQK);
    gate_t<NV,    64,  true ><<<H, 256>>>(H, NQK,      2, 2, outV,  2 * NQK);
    gate_t<NKNOW, 128, false><<<H, 256>>>(H, NQK + NV, 3, 3, outKn, 3 * NQK);

    // Join: main stream waits for side-stream gates before fixup/aux
    cudaStreamWaitEvent(0, evS, 0);

    fixup_kernel<<<256, 256>>>(x, qk, v, kn, outQ, outK, outV, outKn);

    aux_finish_kernel<<<NQK / 256,   256>>>(0,       NQK,   1.0f / NQK,   out + aux_attn_off);
    aux_finish_kernel<<<NQK / 256,   256>>>(NQK,     NQK,   1.0f / NQK,   out + aux_attn_off);
    aux_finish_kernel<<<NV / 256,    256>>>(2 * NQK, NV,    1.0f / NV,    out + aux_attn_off);
    aux_finish_kernel<<<NKNOW / 256, 256>>>(3 * NQK, NKNOW, 1.0f / NKNOW, out + aux_know_off);
}